// round 6
// baseline (speedup 1.0000x reference)
#include <cuda_runtime.h>
#include <cuda_bf16.h>
#include <math.h>
#include <stdint.h>

// Shape (fixed by dataset): N=65536, P=2048, D=64, 10 classes.
#define NPTS 65536
#define PPTS 2048
#define NCLS 10
#define DDIM 64
#define BM 128
#define BN 128
#define LDSS 72              // bf16 per smem row (64 + 8 pad): conflict-free ldmatrix
#define ROWB (LDSS * 2)      // 144 bytes per padded row
#define NBLOCKS (NPTS / BM)  // 512
#define MAXT 26              // max class-padded tiles: 16 + 10 partials
#define PADP (MAXT * BN)     // 3328 padded prototype rows

// __device__ scratch (allocation-free rule)
__device__ __align__(16) __nv_bfloat16 g_pb[PADP * DDIM];  // class-sorted, padded
__device__ __align__(16) float g_p2[PADP];                 // 1e30 on pad rows
__device__ int g_tilecls[MAXT];
__device__ int g_ntiles;
__device__ int g_cls_cnt[NCLS];
__device__ int g_cls_pos[NCLS];
__device__ float g_partial[NBLOCKS];
__device__ unsigned int g_count;   // zero-init; last block resets

// Dynamic smem layout (bytes)
#define SM_B0    0                 // B tile buffer (even t)         18432
#define SM_AB1   18432             // A tile, then B buffer (odd t)  18432
#define SM_PP2   36864             // 2 bufs x 128 f32                1024
#define SM_TCLS  37888             // MAXT ints (padded)               128
#define SM_RED   38016             // [2 grp][2][128] f32             4096
#define SM_XS2   42112             // 128 f32 row norms                512
#define SM_RSUM  42624             // 8 f32
#define SM_FLAG  42656
#define SM_TOTAL 42688

__device__ __forceinline__ void cp16(uint32_t dst, const void* src) {
    asm volatile("cp.async.cg.shared.global [%0], [%1], 16;\n" :: "r"(dst), "l"(src));
}
#define CP_COMMIT() asm volatile("cp.async.commit_group;\n" ::: "memory")
#define CP_WAIT(n)  asm volatile("cp.async.wait_group %0;\n" :: "n"(n) : "memory")

__device__ __forceinline__ uint32_t padoff(int idx) {     // idx-th 16B chunk
    return (uint32_t)((idx >> 3) * ROWB + (idx & 7) * 16);
}
__device__ __forceinline__ uint32_t pk2(float a, float b) {
    __nv_bfloat162 t = __floats2bfloat162_rn(a, b);
    return *(uint32_t*)&t;
}

// ---------------------------------------------------------------------------
// Prep chain (4 tiny kernels): zero pads -> count classes -> offsets/tile
// classes -> scatter prototypes class-grouped (bf16 + norms). Scatter order
// within a class is atomic (non-deterministic) but mins are permutation-
// invariant, so the output is bitwise stable.
// ---------------------------------------------------------------------------
__global__ void prep_zero() {
    int i = blockIdx.x * 256 + threadIdx.x;
    if (i < PADP * DDIM * 2 / 16) ((uint4*)g_pb)[i] = make_uint4(0, 0, 0, 0);
    if (i < PADP) g_p2[i] = 1e30f;
    if (i < NCLS) g_cls_cnt[i] = 0;
}
__global__ void prep_count(const int* __restrict__ plab) {
    int i = blockIdx.x * 256 + threadIdx.x;
    if (i < PPTS) atomicAdd(&g_cls_cnt[plab[i]], 1);
}
__global__ void prep_offset() {
    if (threadIdx.x == 0) {
        int off = 0;
        for (int c = 0; c < NCLS; c++) {
            int cnt = g_cls_cnt[c];
            g_cls_pos[c] = off;
            int t0 = off >> 7, ntc = (cnt + 127) >> 7;
            for (int t = t0; t < t0 + ntc; t++) g_tilecls[t] = c;
            off += ntc << 7;
        }
        g_ntiles = off >> 7;
    }
}
__global__ void prep_scatter(const float* __restrict__ p, const int* __restrict__ plab) {
    int w = (blockIdx.x * blockDim.x + threadIdx.x) >> 5;
    int lane = threadIdx.x & 31;
    if (w >= PPTS) return;
    int pos = 0;
    if (lane == 0) pos = atomicAdd(&g_cls_pos[plab[w]], 1);
    pos = __shfl_sync(0xffffffffu, pos, 0);
    float2 v = ((const float2*)(p + (size_t)w * DDIM))[lane];
    float ss = v.x * v.x + v.y * v.y;
    #pragma unroll
    for (int o = 16; o; o >>= 1) ss += __shfl_xor_sync(0xffffffffu, ss, o);
    ((__nv_bfloat162*)g_pb)[(size_t)pos * (DDIM / 2) + lane] = __floats2bfloat162_rn(v.x, v.y);
    if (lane == 0) g_p2[pos] = ss;
}

// ---------------------------------------------------------------------------
// Main: 128x128-tile bf16 mma.sync GEMM fused with min + loss.
// Prototypes class-sorted & tile-aligned: each tile is ONE class, so the
// epilogue min is unconditional (no per-element label compare); pos/neg
// classification happens once per tile (4 compares).
// ---------------------------------------------------------------------------
__global__ __launch_bounds__(256, 3) void glvq_main(
    const float* __restrict__ x, const int* __restrict__ y,
    float* __restrict__ out) {

    extern __shared__ char sm[];
    const uint32_t smb = (uint32_t)__cvta_generic_to_shared(sm);
    float* red   = (float*)(sm + SM_RED);
    float* xs2   = (float*)(sm + SM_XS2);
    float* rsum  = (float*)(sm + SM_RSUM);
    int*   tclss = (int*)(sm + SM_TCLS);
    int*   flag  = (int*)(sm + SM_FLAG);

    const int tid = threadIdx.x;
    const int warp = tid >> 5, lane = tid & 31;
    const int wm = warp >> 1, wn = warp & 1;
    const int qid = lane >> 2, qtr = lane & 3;
    const int rowBase = blockIdx.x * BM;
    const int nt = g_ntiles;

    // Issue B0 tile + tile-0 norms via cp.async (overlaps x convert).
    {
        #pragma unroll
        for (int i = 0; i < 4; i++) {
            int c = tid + i * 256;
            cp16(smb + SM_B0 + padoff(c), (const char*)g_pb + (size_t)c * 16);
        }
        if (tid < 32) cp16(smb + SM_PP2 + tid * 16, (const char*)g_p2 + tid * 16);
        CP_COMMIT();
    }
    if (tid < nt) tclss[tid] = g_tilecls[tid];

    // Convert this CTA's x tile fp32->bf16 into SM_AB1; row norms.
    {
        const int r = tid >> 1, h = tid & 1;
        const float4* xs4 = (const float4*)(x + (size_t)(rowBase + r) * DDIM + h * 32);
        float ss = 0.f;
        #pragma unroll
        for (int i = 0; i < 4; i++) {
            float4 v0 = xs4[i * 2], v1 = xs4[i * 2 + 1];
            ss += v0.x * v0.x + v0.y * v0.y + v0.z * v0.z + v0.w * v0.w
                + v1.x * v1.x + v1.y * v1.y + v1.z * v1.z + v1.w * v1.w;
            uint4 w;
            w.x = pk2(v0.x, v0.y); w.y = pk2(v0.z, v0.w);
            w.z = pk2(v1.x, v1.y); w.w = pk2(v1.z, v1.w);
            *(uint4*)(sm + SM_AB1 + r * ROWB + h * 64 + i * 16) = w;
        }
        ss += __shfl_xor_sync(0xffffffffu, ss, 1);
        if (h == 0) xs2[r] = ss;
    }

    // Row labels for this thread's accumulator rows.
    int yv[2][2];
    #pragma unroll
    for (int mf = 0; mf < 2; mf++)
        #pragma unroll
        for (int h = 0; h < 2; h++)
            yv[mf][h] = y[rowBase + wm * 32 + mf * 16 + h * 8 + qid];

    float pmin[2][2], nmin[2][2];
    #pragma unroll
    for (int mf = 0; mf < 2; mf++)
        #pragma unroll
        for (int h = 0; h < 2; h++) { pmin[mf][h] = 1e30f; nmin[mf][h] = 1e30f; }

    __syncthreads();   // A tile (STS) + xs2 + tclss visible

    // Hoist A fragments (loop-invariant): 8x ldmatrix.x4 from SM_AB1.
    uint32_t a[2][4][4];
    {
        int arow = (lane & 7) + ((lane >> 3) & 1) * 8;
        int acol = (lane >> 4) * 8;
        #pragma unroll
        for (int mf = 0; mf < 2; mf++)
            #pragma unroll
            for (int kk = 0; kk < 4; kk++) {
                uint32_t ad = smb + SM_AB1
                    + (uint32_t)(wm * 32 + mf * 16 + arow) * ROWB
                    + (uint32_t)(kk * 16 + acol) * 2;
                asm volatile(
                    "ldmatrix.sync.aligned.m8n8.x4.shared.b16 {%0,%1,%2,%3}, [%4];\n"
                    : "=r"(a[mf][kk][0]), "=r"(a[mf][kk][1]),
                      "=r"(a[mf][kk][2]), "=r"(a[mf][kk][3]) : "r"(ad));
            }
    }
    __syncthreads();   // A reads done: SM_AB1 becomes B buffer 1.

    const uint32_t brow_off = (uint32_t)(lane & 7) * ROWB + (uint32_t)((lane >> 3) & 3) * 16;

    for (int t = 0; t < nt; t++) {
        CP_WAIT(0);        // B[t] + norms[t] resident
        __syncthreads();   // visible to all; B[t-1] buffer free

        // Prefetch B[t+1] + norms[t+1] into the other buffer.
        if (t + 1 < nt) {
            const char* src = (const char*)(g_pb + (size_t)(t + 1) * BN * DDIM);
            uint32_t dstb = smb + (((t + 1) & 1) ? SM_AB1 : SM_B0);
            #pragma unroll
            for (int i = 0; i < 4; i++) {
                int c = tid + i * 256;
                cp16(dstb + padoff(c), src + (size_t)c * 16);
            }
            if (tid < 32)
                cp16(smb + SM_PP2 + ((t + 1) & 1) * 512 + tid * 16,
                     (const char*)(g_p2 + (size_t)(t + 1) * BN) + tid * 16);
            CP_COMMIT();
        }

        const int buf = t & 1;
        const uint32_t pbase = smb + (buf ? SM_AB1 : SM_B0)
                             + (uint32_t)(wn * 64) * ROWB + brow_off;
        const float* pp2 = (const float*)(sm + SM_PP2 + buf * 512);

        float tmin[2][2];
        #pragma unroll
        for (int mf = 0; mf < 2; mf++)
            #pragma unroll
            for (int h = 0; h < 2; h++) tmin[mf][h] = 1e30f;

        #pragma unroll
        for (int nf = 0; nf < 8; nf++) {
            uint32_t b[8];
            uint32_t r0 = pbase + (uint32_t)(nf * 8) * ROWB;
            asm volatile(
                "ldmatrix.sync.aligned.m8n8.x4.shared.b16 {%0,%1,%2,%3}, [%4];\n"
                : "=r"(b[0]), "=r"(b[1]), "=r"(b[2]), "=r"(b[3]) : "r"(r0));
            asm volatile(
                "ldmatrix.sync.aligned.m8n8.x4.shared.b16 {%0,%1,%2,%3}, [%4];\n"
                : "=r"(b[4]), "=r"(b[5]), "=r"(b[6]), "=r"(b[7]) : "r"(r0 + 64));

            float c0[4] = {0.f, 0.f, 0.f, 0.f};
            float c1[4] = {0.f, 0.f, 0.f, 0.f};
            #pragma unroll
            for (int kk = 0; kk < 4; kk++) {
                asm volatile(
                    "mma.sync.aligned.m16n8k16.row.col.f32.bf16.bf16.f32 "
                    "{%0,%1,%2,%3}, {%4,%5,%6,%7}, {%8,%9}, {%0,%1,%2,%3};\n"
                    : "+f"(c0[0]), "+f"(c0[1]), "+f"(c0[2]), "+f"(c0[3])
                    : "r"(a[0][kk][0]), "r"(a[0][kk][1]),
                      "r"(a[0][kk][2]), "r"(a[0][kk][3]),
                      "r"(b[kk * 2]), "r"(b[kk * 2 + 1]));
                asm volatile(
                    "mma.sync.aligned.m16n8k16.row.col.f32.bf16.bf16.f32 "
                    "{%0,%1,%2,%3}, {%4,%5,%6,%7}, {%8,%9}, {%0,%1,%2,%3};\n"
                    : "+f"(c1[0]), "+f"(c1[1]), "+f"(c1[2]), "+f"(c1[3])
                    : "r"(a[1][kk][0]), "r"(a[1][kk][1]),
                      "r"(a[1][kk][2]), "r"(a[1][kk][3]),
                      "r"(b[kk * 2]), "r"(b[kk * 2 + 1]));
            }

            // Unconditional per-tile mins (tile is single-class).
            const int jc = wn * 64 + nf * 8 + qtr * 2;
            float2 pp = *(const float2*)(pp2 + jc);
            tmin[0][0] = fminf(tmin[0][0], fmaf(-2.f, c0[0], pp.x));
            tmin[0][0] = fminf(tmin[0][0], fmaf(-2.f, c0[1], pp.y));
            tmin[0][1] = fminf(tmin[0][1], fmaf(-2.f, c0[2], pp.x));
            tmin[0][1] = fminf(tmin[0][1], fmaf(-2.f, c0[3], pp.y));
            tmin[1][0] = fminf(tmin[1][0], fmaf(-2.f, c1[0], pp.x));
            tmin[1][0] = fminf(tmin[1][0], fmaf(-2.f, c1[1], pp.y));
            tmin[1][1] = fminf(tmin[1][1], fmaf(-2.f, c1[2], pp.x));
            tmin[1][1] = fminf(tmin[1][1], fmaf(-2.f, c1[3], pp.y));
        }

        // Per-tile classification: 4 compares instead of 256.
        const int tc = tclss[t];
        #pragma unroll
        for (int mf = 0; mf < 2; mf++)
            #pragma unroll
            for (int h = 0; h < 2; h++) {
                if (tc == yv[mf][h]) pmin[mf][h] = fminf(pmin[mf][h], tmin[mf][h]);
                else                 nmin[mf][h] = fminf(nmin[mf][h], tmin[mf][h]);
            }
    }

    // Quad reduction (same rows, different cols across 4 lanes).
    #pragma unroll
    for (int mf = 0; mf < 2; mf++)
        #pragma unroll
        for (int h = 0; h < 2; h++) {
            #pragma unroll
            for (int o = 1; o <= 2; o <<= 1) {
                pmin[mf][h] = fminf(pmin[mf][h], __shfl_xor_sync(0xffffffffu, pmin[mf][h], o));
                nmin[mf][h] = fminf(nmin[mf][h], __shfl_xor_sync(0xffffffffu, nmin[mf][h], o));
            }
        }
    __syncthreads();
    if (qtr == 0) {
        #pragma unroll
        for (int mf = 0; mf < 2; mf++)
            #pragma unroll
            for (int h = 0; h < 2; h++) {
                int r = wm * 32 + mf * 16 + h * 8 + qid;
                red[(wn * 2 + 0) * BM + r] = pmin[mf][h];
                red[(wn * 2 + 1) * BM + r] = nmin[mf][h];
            }
    }
    __syncthreads();

    float mysum = 0.f;
    if (tid < BM) {
        float spos = fminf(red[0 * BM + tid], red[2 * BM + tid]);
        float sneg = fminf(red[1 * BM + tid], red[3 * BM + tid]);
        float x2 = xs2[tid];
        float pos = sqrtf(fmaxf(spos + x2, 0.f));
        float neg = sqrtf(fmaxf(sneg + x2, 0.f));
        float mu = (pos - neg) / (pos + neg);
        mysum = 1.f / (1.f + expf(-mu));
    }
    #pragma unroll
    for (int o = 16; o; o >>= 1) mysum += __shfl_xor_sync(0xffffffffu, mysum, o);
    if (lane == 0) rsum[warp] = mysum;
    __syncthreads();
    if (tid == 0) {
        float s = 0.f;
        #pragma unroll
        for (int i = 0; i < 8; i++) s += rsum[i];
        g_partial[blockIdx.x] = s;
        __threadfence();
        unsigned int ticket = atomicAdd(&g_count, 1);
        *flag = (ticket == gridDim.x - 1) ? 1 : 0;
    }
    __syncthreads();

    if (*flag) {   // last block: deterministic final mean
        float s = 0.f;
        for (int i = tid; i < NBLOCKS; i += 256) s += __ldcg(&g_partial[i]);
        #pragma unroll
        for (int o = 16; o; o >>= 1) s += __shfl_xor_sync(0xffffffffu, s, o);
        if (lane == 0) rsum[warp] = s;
        __syncthreads();
        if (tid == 0) {
            float tot = 0.f;
            #pragma unroll
            for (int i = 0; i < 8; i++) tot += rsum[i];
            out[0] = tot * (1.0f / (float)NPTS);
            g_count = 0;   // reset for next graph replay
        }
    }
}

extern "C" void kernel_launch(void* const* d_in, const int* in_sizes, int n_in,
                              void* d_out, int out_size) {
    const float* x    = (const float*)d_in[0];
    const int*   yy   = (const int*)d_in[1];
    const float* prot = (const float*)d_in[2];
    const int*   plab = (const int*)d_in[3];
    float* out = (float*)d_out;

    cudaFuncSetAttribute(glvq_main, cudaFuncAttributeMaxDynamicSharedMemorySize, SM_TOTAL);

    prep_zero<<<(PADP * DDIM * 2 / 16 + 255) / 256, 256>>>();
    prep_count<<<(PPTS + 255) / 256, 256>>>(plab);
    prep_offset<<<1, 32>>>();
    prep_scatter<<<PPTS / 8, 256>>>(prot, plab);
    glvq_main<<<NBLOCKS, 256, SM_TOTAL>>>(x, yy, out);
}

// round 7
// speedup vs baseline: 1.1626x; 1.1626x over previous
#include <cuda_runtime.h>
#include <cuda_bf16.h>
#include <math.h>
#include <stdint.h>

// Shape (fixed by dataset): N=65536, P=2048, D=64, 10 classes.
#define NPTS 65536
#define PPTS 2048
#define DDIM 64
#define BM 128
#define BN 128
#define LDSS 72              // bf16 per smem row (64 + 8 pad): conflict-free ldmatrix
#define ROWB (LDSS * 2)      // 144 bytes per padded row
#define NTILES (PPTS / BN)   // 16
#define NBLOCKS (NPTS / BM)  // 512

// __device__ scratch (allocation-free rule). Only prototypes staged.
__device__ __align__(16) __nv_bfloat16 g_pb[PPTS * DDIM];
__device__ __align__(16) float g_p2[PPTS];
__device__ float g_partial[NBLOCKS];
__device__ unsigned int g_count;   // zero-init; last block resets

// Dynamic smem layout (bytes)
#define SM_B0    0                 // B tile buffer (even t)         18432
#define SM_AB1   18432             // A tile, then B buffer (odd t)  18432
#define SM_PP2   36864             // 2 bufs x 128 f32                1024
#define SM_PPL   37888             // 2 bufs x 128 i32                1024
#define SM_RED   38912             // [2 grp][2][128] f32             4096
#define SM_XS2   43008             // 128 f32 row norms                512
#define SM_RSUM  43520             // 8 f32
#define SM_FLAG  43552
#define SM_TOTAL 43584

__device__ __forceinline__ void cp16(uint32_t dst, const void* src) {
    asm volatile("cp.async.cg.shared.global [%0], [%1], 16;\n" :: "r"(dst), "l"(src));
}
#define CP_COMMIT() asm volatile("cp.async.commit_group;\n" ::: "memory")
#define CP_WAIT(n)  asm volatile("cp.async.wait_group %0;\n" :: "n"(n) : "memory")

__device__ __forceinline__ uint32_t padoff(int idx) {     // idx-th 16B chunk
    return (uint32_t)((idx >> 3) * ROWB + (idx & 7) * 16);
}
__device__ __forceinline__ uint32_t pk2(float a, float b) {
    __nv_bfloat162 t = __floats2bfloat162_rn(a, b);
    return *(uint32_t*)&t;
}
#define LDSMX4(rr, addr) asm volatile( \
    "ldmatrix.sync.aligned.m8n8.x4.shared.b16 {%0,%1,%2,%3}, [%4];\n" \
    : "=r"((rr)[0]), "=r"((rr)[1]), "=r"((rr)[2]), "=r"((rr)[3]) : "r"(addr))
#define MMA16816(cc, aa, b0, b1) asm volatile( \
    "mma.sync.aligned.m16n8k16.row.col.f32.bf16.bf16.f32 " \
    "{%0,%1,%2,%3}, {%4,%5,%6,%7}, {%8,%9}, {%0,%1,%2,%3};\n" \
    : "+f"((cc)[0]), "+f"((cc)[1]), "+f"((cc)[2]), "+f"((cc)[3]) \
    : "r"((aa)[0]), "r"((aa)[1]), "r"((aa)[2]), "r"((aa)[3]), "r"(b0), "r"(b1))

// ---------------------------------------------------------------------------
// Prep (prototypes only): fp32 rows -> bf16 rows + row sum-of-squares.
// ---------------------------------------------------------------------------
__global__ void prep_proto(const float* __restrict__ p) {
    int w = (blockIdx.x * blockDim.x + threadIdx.x) >> 5;
    int lane = threadIdx.x & 31;
    if (w >= PPTS) return;
    float2 v = ((const float2*)(p + (size_t)w * DDIM))[lane];
    float ss = v.x * v.x + v.y * v.y;
    #pragma unroll
    for (int o = 16; o; o >>= 1) ss += __shfl_xor_sync(0xffffffffu, ss, o);
    ((__nv_bfloat162*)g_pb)[(size_t)w * (DDIM / 2) + lane] = __floats2bfloat162_rn(v.x, v.y);
    if (lane == 0) g_p2[w] = ss;
}

// ---------------------------------------------------------------------------
// Main: 128x128-tile bf16 mma.sync GEMM fused with masked min + loss.
// Software-pipelined slab loop: LDSM prefetch one slab ahead; epilogue of
// slab nf-1 issues in the latency shadow of slab nf's MMA chain.
// ---------------------------------------------------------------------------
__global__ __launch_bounds__(256, 3) void glvq_main(
    const float* __restrict__ x, const int* __restrict__ y,
    const int* __restrict__ plab, float* __restrict__ out) {

    extern __shared__ char sm[];
    const uint32_t smb = (uint32_t)__cvta_generic_to_shared(sm);
    float* red  = (float*)(sm + SM_RED);
    float* xs2  = (float*)(sm + SM_XS2);
    float* rsum = (float*)(sm + SM_RSUM);
    int*   flag = (int*)(sm + SM_FLAG);

    const int tid = threadIdx.x;
    const int warp = tid >> 5, lane = tid & 31;
    const int wm = warp >> 1, wn = warp & 1;
    const int qid = lane >> 2, qtr = lane & 3;
    const int rowBase = blockIdx.x * BM;

    // Issue B0 tile + tile-0 metadata via cp.async (overlaps x convert).
    {
        #pragma unroll
        for (int i = 0; i < 4; i++) {
            int c = tid + i * 256;
            cp16(smb + SM_B0 + padoff(c), (const char*)g_pb + (size_t)c * 16);
        }
        if (tid < 32)      cp16(smb + SM_PP2 + tid * 16, (const char*)g_p2 + tid * 16);
        else if (tid < 64) cp16(smb + SM_PPL + (tid - 32) * 16,
                                (const char*)plab + (tid - 32) * 16);
        CP_COMMIT();
    }

    // Convert this CTA's x tile fp32->bf16 into SM_AB1; row norms.
    {
        const int r = tid >> 1, h = tid & 1;
        const float4* xs4 = (const float4*)(x + (size_t)(rowBase + r) * DDIM + h * 32);
        float ss = 0.f;
        #pragma unroll
        for (int i = 0; i < 4; i++) {
            float4 v0 = xs4[i * 2], v1 = xs4[i * 2 + 1];
            ss += v0.x * v0.x + v0.y * v0.y + v0.z * v0.z + v0.w * v0.w
                + v1.x * v1.x + v1.y * v1.y + v1.z * v1.z + v1.w * v1.w;
            uint4 w;
            w.x = pk2(v0.x, v0.y); w.y = pk2(v0.z, v0.w);
            w.z = pk2(v1.x, v1.y); w.w = pk2(v1.z, v1.w);
            *(uint4*)(sm + SM_AB1 + r * ROWB + h * 64 + i * 16) = w;
        }
        ss += __shfl_xor_sync(0xffffffffu, ss, 1);
        if (h == 0) xs2[r] = ss;
    }

    // Row labels for this thread's accumulator rows.
    int yv[2][2];
    #pragma unroll
    for (int mf = 0; mf < 2; mf++)
        #pragma unroll
        for (int h = 0; h < 2; h++)
            yv[mf][h] = y[rowBase + wm * 32 + mf * 16 + h * 8 + qid];

    float pmin[2][2], nmin[2][2];
    #pragma unroll
    for (int mf = 0; mf < 2; mf++)
        #pragma unroll
        for (int h = 0; h < 2; h++) { pmin[mf][h] = 1e30f; nmin[mf][h] = 1e30f; }

    __syncthreads();   // A tile (STS) + xs2 visible

    // Hoist A fragments (loop-invariant): 8x ldmatrix.x4 from SM_AB1.
    uint32_t a[2][4][4];
    {
        int arow = (lane & 7) + ((lane >> 3) & 1) * 8;
        int acol = (lane >> 4) * 8;
        #pragma unroll
        for (int mf = 0; mf < 2; mf++)
            #pragma unroll
            for (int kk = 0; kk < 4; kk++) {
                uint32_t ad = smb + SM_AB1
                    + (uint32_t)(wm * 32 + mf * 16 + arow) * ROWB
                    + (uint32_t)(kk * 16 + acol) * 2;
                LDSMX4(a[mf][kk], ad);
            }
    }
    __syncthreads();   // A reads done: SM_AB1 becomes B buffer 1.

    const uint32_t brow_off = (uint32_t)(lane & 7) * ROWB + (uint32_t)((lane >> 3) & 3) * 16;

    for (int t = 0; t < NTILES; t++) {
        CP_WAIT(0);        // B[t] + meta[t] resident
        __syncthreads();   // visible to all; B[t-1] buffer free

        // Prefetch B[t+1] + meta[t+1] into the other buffer.
        if (t + 1 < NTILES) {
            const char* src = (const char*)(g_pb + (size_t)(t + 1) * BN * DDIM);
            uint32_t dstb = smb + (((t + 1) & 1) ? SM_AB1 : SM_B0);
            #pragma unroll
            for (int i = 0; i < 4; i++) {
                int c = tid + i * 256;
                cp16(dstb + padoff(c), src + (size_t)c * 16);
            }
            uint32_t mb = ((t + 1) & 1) * 512;
            if (tid < 32)
                cp16(smb + SM_PP2 + mb + tid * 16,
                     (const char*)(g_p2 + (size_t)(t + 1) * BN) + tid * 16);
            else if (tid < 64)
                cp16(smb + SM_PPL + mb + (tid - 32) * 16,
                     (const char*)(plab + (size_t)(t + 1) * BN) + (tid - 32) * 16);
            CP_COMMIT();
        }

        const int buf = t & 1;
        const uint32_t pbase = smb + (buf ? SM_AB1 : SM_B0)
                             + (uint32_t)(wn * 64) * ROWB + brow_off;
        const float* pp2 = (const float*)(sm + SM_PP2 + buf * 512);
        const int*   ppl = (const int*)(sm + SM_PPL + buf * 512);

        // ---- software-pipelined slab loop ----
        uint32_t b[2][8];
        LDSMX4(b[0],     pbase);
        LDSMX4(b[0] + 4, pbase + 64);

        float pc0[4], pc1[4];   // previous slab's accumulators

        #pragma unroll
        for (int nf = 0; nf < 8; nf++) {
            const int cur = nf & 1;
            // Prefetch B fragments for slab nf+1 (full-slab LDS shadow).
            if (nf < 7) {
                uint32_t r0 = pbase + (uint32_t)((nf + 1) * 8) * ROWB;
                LDSMX4(b[cur ^ 1],     r0);
                LDSMX4(b[cur ^ 1] + 4, r0 + 64);
            }
            // MMA chain for slab nf (b[cur] loaded one iteration ago).
            float c0[4] = {0.f, 0.f, 0.f, 0.f};
            float c1[4] = {0.f, 0.f, 0.f, 0.f};
            #pragma unroll
            for (int kk = 0; kk < 4; kk++) {
                MMA16816(c0, a[0][kk], b[cur][kk * 2], b[cur][kk * 2 + 1]);
                MMA16816(c1, a[1][kk], b[cur][kk * 2], b[cur][kk * 2 + 1]);
            }
            // Epilogue for slab nf-1 — fills slab nf's MMA latency shadow.
            if (nf > 0) {
                const int jc = wn * 64 + (nf - 1) * 8 + qtr * 2;
                float2 pp = *(const float2*)(pp2 + jc);
                int2   ll = *(const int2*)(ppl + jc);
                float s00 = fmaf(-2.f, pc0[0], pp.x);
                float s01 = fmaf(-2.f, pc0[1], pp.y);
                float s02 = fmaf(-2.f, pc0[2], pp.x);
                float s03 = fmaf(-2.f, pc0[3], pp.y);
                float s10 = fmaf(-2.f, pc1[0], pp.x);
                float s11 = fmaf(-2.f, pc1[1], pp.y);
                float s12 = fmaf(-2.f, pc1[2], pp.x);
                float s13 = fmaf(-2.f, pc1[3], pp.y);
                if (ll.x == yv[0][0]) pmin[0][0] = fminf(pmin[0][0], s00);
                else                  nmin[0][0] = fminf(nmin[0][0], s00);
                if (ll.y == yv[0][0]) pmin[0][0] = fminf(pmin[0][0], s01);
                else                  nmin[0][0] = fminf(nmin[0][0], s01);
                if (ll.x == yv[0][1]) pmin[0][1] = fminf(pmin[0][1], s02);
                else                  nmin[0][1] = fminf(nmin[0][1], s02);
                if (ll.y == yv[0][1]) pmin[0][1] = fminf(pmin[0][1], s03);
                else                  nmin[0][1] = fminf(nmin[0][1], s03);
                if (ll.x == yv[1][0]) pmin[1][0] = fminf(pmin[1][0], s10);
                else                  nmin[1][0] = fminf(nmin[1][0], s10);
                if (ll.y == yv[1][0]) pmin[1][0] = fminf(pmin[1][0], s11);
                else                  nmin[1][0] = fminf(nmin[1][0], s11);
                if (ll.x == yv[1][1]) pmin[1][1] = fminf(pmin[1][1], s12);
                else                  nmin[1][1] = fminf(nmin[1][1], s12);
                if (ll.y == yv[1][1]) pmin[1][1] = fminf(pmin[1][1], s13);
                else                  nmin[1][1] = fminf(nmin[1][1], s13);
            }
            #pragma unroll
            for (int i = 0; i < 4; i++) { pc0[i] = c0[i]; pc1[i] = c1[i]; }
        }
        // Drain: epilogue for slab 7.
        {
            const int jc = wn * 64 + 7 * 8 + qtr * 2;
            float2 pp = *(const float2*)(pp2 + jc);
            int2   ll = *(const int2*)(ppl + jc);
            float s00 = fmaf(-2.f, pc0[0], pp.x);
            float s01 = fmaf(-2.f, pc0[1], pp.y);
            float s02 = fmaf(-2.f, pc0[2], pp.x);
            float s03 = fmaf(-2.f, pc0[3], pp.y);
            float s10 = fmaf(-2.f, pc1[0], pp.x);
            float s11 = fmaf(-2.f, pc1[1], pp.y);
            float s12 = fmaf(-2.f, pc1[2], pp.x);
            float s13 = fmaf(-2.f, pc1[3], pp.y);
            if (ll.x == yv[0][0]) pmin[0][0] = fminf(pmin[0][0], s00);
            else                  nmin[0][0] = fminf(nmin[0][0], s00);
            if (ll.y == yv[0][0]) pmin[0][0] = fminf(pmin[0][0], s01);
            else                  nmin[0][0] = fminf(nmin[0][0], s01);
            if (ll.x == yv[0][1]) pmin[0][1] = fminf(pmin[0][1], s02);
            else                  nmin[0][1] = fminf(nmin[0][1], s02);
            if (ll.y == yv[0][1]) pmin[0][1] = fminf(pmin[0][1], s03);
            else                  nmin[0][1] = fminf(nmin[0][1], s03);
            if (ll.x == yv[1][0]) pmin[1][0] = fminf(pmin[1][0], s10);
            else                  nmin[1][0] = fminf(nmin[1][0], s10);
            if (ll.y == yv[1][0]) pmin[1][0] = fminf(pmin[1][0], s11);
            else                  nmin[1][0] = fminf(nmin[1][0], s11);
            if (ll.x == yv[1][1]) pmin[1][1] = fminf(pmin[1][1], s12);
            else                  nmin[1][1] = fminf(nmin[1][1], s12);
            if (ll.y == yv[1][1]) pmin[1][1] = fminf(pmin[1][1], s13);
            else                  nmin[1][1] = fminf(nmin[1][1], s13);
        }
    }

    // Quad reduction (same rows, different cols across 4 lanes).
    #pragma unroll
    for (int mf = 0; mf < 2; mf++)
        #pragma unroll
        for (int h = 0; h < 2; h++) {
            #pragma unroll
            for (int o = 1; o <= 2; o <<= 1) {
                pmin[mf][h] = fminf(pmin[mf][h], __shfl_xor_sync(0xffffffffu, pmin[mf][h], o));
                nmin[mf][h] = fminf(nmin[mf][h], __shfl_xor_sync(0xffffffffu, nmin[mf][h], o));
            }
        }
    __syncthreads();
    if (qtr == 0) {
        #pragma unroll
        for (int mf = 0; mf < 2; mf++)
            #pragma unroll
            for (int h = 0; h < 2; h++) {
                int r = wm * 32 + mf * 16 + h * 8 + qid;
                red[(wn * 2 + 0) * BM + r] = pmin[mf][h];
                red[(wn * 2 + 1) * BM + r] = nmin[mf][h];
            }
    }
    __syncthreads();

    float mysum = 0.f;
    if (tid < BM) {
        float spos = fminf(red[0 * BM + tid], red[2 * BM + tid]);
        float sneg = fminf(red[1 * BM + tid], red[3 * BM + tid]);
        float x2 = xs2[tid];
        float pos = sqrtf(fmaxf(spos + x2, 0.f));
        float neg = sqrtf(fmaxf(sneg + x2, 0.f));
        float mu = (pos - neg) / (pos + neg);
        mysum = 1.f / (1.f + expf(-mu));
    }
    #pragma unroll
    for (int o = 16; o; o >>= 1) mysum += __shfl_xor_sync(0xffffffffu, mysum, o);
    if (lane == 0) rsum[warp] = mysum;
    __syncthreads();
    if (tid == 0) {
        float s = 0.f;
        #pragma unroll
        for (int i = 0; i < 8; i++) s += rsum[i];
        g_partial[blockIdx.x] = s;
        __threadfence();
        unsigned int ticket = atomicAdd(&g_count, 1);
        *flag = (ticket == gridDim.x - 1) ? 1 : 0;
    }
    __syncthreads();

    if (*flag) {   // last block: deterministic final mean
        float s = 0.f;
        for (int i = tid; i < NBLOCKS; i += 256) s += __ldcg(&g_partial[i]);
        #pragma unroll
        for (int o = 16; o; o >>= 1) s += __shfl_xor_sync(0xffffffffu, s, o);
        if (lane == 0) rsum[warp] = s;
        __syncthreads();
        if (tid == 0) {
            float tot = 0.f;
            #pragma unroll
            for (int i = 0; i < 8; i++) tot += rsum[i];
            out[0] = tot * (1.0f / (float)NPTS);
            g_count = 0;   // reset for next graph replay
        }
    }
}

extern "C" void kernel_launch(void* const* d_in, const int* in_sizes, int n_in,
                              void* d_out, int out_size) {
    const float* x    = (const float*)d_in[0];
    const int*   yy   = (const int*)d_in[1];
    const float* prot = (const float*)d_in[2];
    const int*   plab = (const int*)d_in[3];
    float* out = (float*)d_out;

    cudaFuncSetAttribute(glvq_main, cudaFuncAttributeMaxDynamicSharedMemorySize, SM_TOTAL);

    prep_proto<<<PPTS / 8, 256>>>(prot);
    glvq_main<<<NBLOCKS, 256, SM_TOTAL>>>(x, yy, plab, out);
}